// round 2
// baseline (speedup 1.0000x reference)
#include <cuda_runtime.h>
#include <cuda_bf16.h>

#define Bn 1024
#define Dn 512
#define On 256

// ---------------- device scratch (no allocations allowed) ----------------
__device__ double g_Sx[Dn];                 // sum_b (1 - x[b,d])
__device__ double g_Sw[On];                 // sum_d (1 - w[d,o])
__device__ float  g_relx[Dn * On];          // rel_x[d,o]
__device__ float  g_ws[On * Dn];            // per-o sorted-ascending w column
__device__ double g_suf[On * (Dn + 1)];     // per-o suffix sums of sorted w
__device__ float  g_pmin[On * Dn];          // per-o prefix min of w in original order

// ---------------- Sx ----------------
__global__ void k_prepx(const float* __restrict__ x) {
    int d = blockIdx.x * blockDim.x + threadIdx.x;
    if (d < Dn) {
        double s = 0.0;
        for (int b = 0; b < Bn; b++) s += (double)(1.0f - x[b * Dn + d]);
        g_Sx[d] = s;
    }
}

// ---------------- per-o: sort w column, suffix sums, prefix min, Sw -------
__global__ void k_prepw(const float* __restrict__ w) {
    int o = blockIdx.x;
    int tid = threadIdx.x;
    __shared__ float sv[Dn];
    __shared__ float ss[Dn];
    for (int i = tid; i < Dn; i += blockDim.x) {
        float v = w[i * On + o];
        sv[i] = v;
        ss[i] = v;
    }
    __syncthreads();
    // bitonic sort ascending (n=512, 256 threads)
    for (int k = 2; k <= Dn; k <<= 1) {
        for (int j = k >> 1; j > 0; j >>= 1) {
            for (int t2 = tid; t2 < Dn; t2 += blockDim.x) {
                int ixj = t2 ^ j;
                if (ixj > t2) {
                    bool up = ((t2 & k) == 0);
                    float a = ss[t2], b2 = ss[ixj];
                    if ((a > b2) == up) { ss[t2] = b2; ss[ixj] = a; }
                }
            }
            __syncthreads();
        }
    }
    // sorted column out (parallel)
    for (int i = tid; i < Dn; i += blockDim.x) g_ws[o * Dn + i] = ss[i];
    // serial tail for exactness (double accumulation, order-sensitive prefix min)
    if (tid == 0) {
        double s = 0.0;
        float m = 3.0e38f;
        for (int d = 0; d < Dn; d++) {
            float v = sv[d];
            s += (double)(1.0f - v);
            m = fminf(m, v);
            g_pmin[o * Dn + d] = m;
        }
        g_Sw[o] = s;
        double acc = 0.0;
        g_suf[o * (Dn + 1) + Dn] = 0.0;
        for (int i = Dn - 1; i >= 0; i--) {
            acc += (double)ss[i];
            g_suf[o * (Dn + 1) + i] = acc;
        }
    }
}

// ---------------- rel_x[d,o] = 1 - (B - sum_b max(x,t)) / Sx[d] ----------
// grid (O/32, D/32) = (8,16); block 256 = 16x16; micro 2x2 (d x o)
__global__ void k_relx(const float* __restrict__ x, const float* __restrict__ t) {
    int o0 = blockIdx.x * 32;
    int d0 = blockIdx.y * 32;
    __shared__ float xs[32][34];  // [b][d]
    __shared__ float ts[32][34];  // [b][o]
    int tid = threadIdx.x;
    int tx = tid & 15;   // o pair
    int ty = tid >> 4;   // d pair
    double a00 = 0, a01 = 0, a10 = 0, a11 = 0;
    for (int bc = 0; bc < Bn; bc += 32) {
        __syncthreads();
        for (int idx = tid; idx < 1024; idx += 256) {
            int i = idx >> 5, j = idx & 31;
            xs[i][j] = x[(bc + i) * Dn + d0 + j];
            ts[i][j] = t[(bc + i) * On + o0 + j];
        }
        __syncthreads();
        float f00 = 0, f01 = 0, f10 = 0, f11 = 0;
#pragma unroll
        for (int kb = 0; kb < 32; kb++) {
            float2 xv = *(const float2*)&xs[kb][2 * ty];
            float2 tv = *(const float2*)&ts[kb][2 * tx];
            f00 += fmaxf(xv.x, tv.x);
            f01 += fmaxf(xv.x, tv.y);
            f10 += fmaxf(xv.y, tv.x);
            f11 += fmaxf(xv.y, tv.y);
        }
        a00 += (double)f00; a01 += (double)f01;
        a10 += (double)f10; a11 += (double)f11;
    }
    int d_ = d0 + 2 * ty;
    int o_ = o0 + 2 * tx;
    double sx0 = g_Sx[d_], sx1 = g_Sx[d_ + 1];
    g_relx[d_ * On + o_]           = (float)(1.0 - ((double)Bn - a00) / sx0);
    g_relx[d_ * On + o_ + 1]       = (float)(1.0 - ((double)Bn - a01) / sx0);
    g_relx[(d_ + 1) * On + o_]     = (float)(1.0 - ((double)Bn - a10) / sx1);
    g_relx[(d_ + 1) * On + o_ + 1] = (float)(1.0 - ((double)Bn - a11) / sx1);
}

// ---------------- ind_x + chosen_x ----------------
// grid (O/32, B/32) = (8,32); block 256 = 16x16; micro 2x2 (b x o)
__global__ void k_indx(const float* __restrict__ x, const float* __restrict__ w,
                       float* __restrict__ out) {
    int o0 = blockIdx.x * 32;
    int b0 = blockIdx.y * 32;
    __shared__ float xs[32][34];  // [b][d-chunk]
    __shared__ float rs[32][34];  // [d-chunk][o]
    int tid = threadIdx.x;
    int tx = tid & 15;   // o pair
    int ty = tid >> 4;   // b pair
    float v00 = 3.0e38f, v01 = 3.0e38f, v10 = 3.0e38f, v11 = 3.0e38f;
    int i00 = 0, i01 = 0, i10 = 0, i11 = 0;
    for (int dc = 0; dc < Dn; dc += 32) {
        __syncthreads();
        for (int idx = tid; idx < 1024; idx += 256) {
            int i = idx >> 5, j = idx & 31;
            xs[i][j] = x[(b0 + i) * Dn + dc + j];
            rs[i][j] = g_relx[(dc + i) * On + o0 + j];
        }
        __syncthreads();
#pragma unroll
        for (int kd = 0; kd < 32; kd++) {
            float xv0 = xs[2 * ty][kd];
            float xv1 = xs[2 * ty + 1][kd];
            float2 rv = *(const float2*)&rs[kd][2 * tx];
            int dg = dc + kd;
            float v;
            v = fmaxf(xv0, rv.x); if (v < v00) { v00 = v; i00 = dg; }
            v = fmaxf(xv0, rv.y); if (v < v01) { v01 = v; i01 = dg; }
            v = fmaxf(xv1, rv.x); if (v < v10) { v10 = v; i10 = dg; }
            v = fmaxf(xv1, rv.y); if (v < v11) { v11 = v; i11 = dg; }
        }
    }
    int b_ = b0 + 2 * ty;
    int o_ = o0 + 2 * tx;
    out[b_ * On + o_]           = fmaxf(x[b_ * Dn + i00], w[i00 * On + o_]);
    out[b_ * On + o_ + 1]       = fmaxf(x[b_ * Dn + i01], w[i01 * On + o_ + 1]);
    out[(b_ + 1) * On + o_]     = fmaxf(x[(b_ + 1) * Dn + i10], w[i10 * On + o_]);
    out[(b_ + 1) * On + o_ + 1] = fmaxf(x[(b_ + 1) * Dn + i11], w[i11 * On + o_ + 1]);
}

// ---------------- rel_w / ind_w / chosen_w via sorted + prefix-min -------
// grid 256 (one block per o), 256 threads, each handles 4 b's
__global__ void k_wout(const float* __restrict__ x, const float* __restrict__ w,
                       const float* __restrict__ t, float* __restrict__ out) {
    int o = blockIdx.x;
    int tid = threadIdx.x;
    __shared__ float  ws[Dn];
    __shared__ float  pm[Dn];
    __shared__ double suf[Dn + 1];
    for (int i = tid; i < Dn; i += blockDim.x) {
        ws[i] = g_ws[o * Dn + i];
        pm[i] = g_pmin[o * Dn + i];
    }
    for (int i = tid; i < Dn + 1; i += blockDim.x)
        suf[i] = g_suf[o * (Dn + 1) + i];
    __syncthreads();
    double Sw = g_Sw[o];
    float gm = pm[Dn - 1];  // global min of column
    for (int b = tid; b < Bn; b += blockDim.x) {
        float tv = t[b * On + o];
        // c = count of sorted w <= tv
        int lo = 0, hi = Dn;
        while (lo < hi) {
            int m = (lo + hi) >> 1;
            if (ws[m] <= tv) lo = m + 1; else hi = m;
        }
        int c = lo;
        double N = (double)c * (double)tv + suf[c];
        float thr = (float)(1.0 - ((double)Dn - N) / Sw);  // rel_w
        int ind;
        if (pm[Dn - 1] <= thr) {
            // first d with w[d,o] <= thr
            lo = 0; hi = Dn - 1;
            while (lo < hi) {
                int m = (lo + hi) >> 1;
                if (pm[m] <= thr) hi = m; else lo = m + 1;
            }
            ind = lo;
        } else {
            // first argmin of w[:,o]
            lo = 0; hi = Dn - 1;
            while (lo < hi) {
                int m = (lo + hi) >> 1;
                if (pm[m] <= gm) hi = m; else lo = m + 1;
            }
            ind = lo;
        }
        out[Bn * On + b * On + o] = fmaxf(x[b * Dn + ind], w[ind * On + o]);
    }
}

extern "C" void kernel_launch(void* const* d_in, const int* in_sizes, int n_in,
                              void* d_out, int out_size) {
    (void)in_sizes; (void)n_in; (void)out_size;
    const float* x = (const float*)d_in[0];
    const float* w = (const float*)d_in[1];
    const float* t = (const float*)d_in[2];
    float* out = (float*)d_out;

    k_prepx<<<2, 256>>>(x);
    k_prepw<<<On, 256>>>(w);
    k_relx<<<dim3(On / 32, Dn / 32), 256>>>(x, t);
    k_indx<<<dim3(On / 32, Bn / 32), 256>>>(x, w, out);
    k_wout<<<On, 256>>>(x, w, t, out);
}

// round 3
// speedup vs baseline: 1.6684x; 1.6684x over previous
#include <cuda_runtime.h>
#include <cuda_bf16.h>

#define Bn 1024
#define Dn 512
#define On 256
#define BO (Bn * On)
#define DO (Dn * On)

// ---------------- device scratch (no allocations allowed) ----------------
__device__ float  g_SxP[8 * Dn];            // partial sums of (1-x) per 128-b chunk
__device__ double g_Sx[Dn];                 // sum_b (1 - x[b,d])
__device__ double g_Sw[On];                 // sum_d (1 - w[d,o])
__device__ double g_rxp[4 * DO];            // rel_x numerator partials (per 256-b split)
__device__ float  g_relx[DO];               // rel_x[d,o]
__device__ float  g_vp[4 * BO];             // ind_x partial min values (per 128-d split)
__device__ int    g_ip[4 * BO];             // ind_x partial argmin
__device__ float  g_ws[On * Dn];            // per-o sorted-ascending w column
__device__ double g_suf[On * (Dn + 1)];     // per-o suffix sums of sorted w
__device__ float  g_pmin[On * Dn];          // per-o prefix min of w in original order

// ---------------- Sx partials: tiled transpose reduction -----------------
// grid (Dn/32=16, 8 b-splits), block 256 (32 d x 8 rows)
__global__ __launch_bounds__(256) void k_prepx_part(const float* __restrict__ x) {
    int d0 = blockIdx.x * 32;
    int bs = blockIdx.y;                  // 128 b's per split
    int dt = threadIdx.x & 31;
    int rt = threadIdx.x >> 5;            // 0..7
    int b0 = bs * 128 + rt * 16;
    float s = 0.0f;
#pragma unroll
    for (int k = 0; k < 16; k++)
        s += 1.0f - x[(b0 + k) * Dn + d0 + dt];
    __shared__ float sh[8][33];
    sh[rt][dt] = s;
    __syncthreads();
    if (rt == 0) {
        float acc = 0.0f;
#pragma unroll
        for (int r = 0; r < 8; r++) acc += sh[r][dt];
        g_SxP[bs * Dn + d0 + dt] = acc;
    }
}

__global__ __launch_bounds__(256) void k_combSx() {
    int d = blockIdx.x * 256 + threadIdx.x;
    if (d < Dn) {
        double s = 0.0;
#pragma unroll
        for (int i = 0; i < 8; i++) s += (double)g_SxP[i * Dn + d];
        g_Sx[d] = s;
    }
}

// ---------------- per-o: sort w column, suffix sums, prefix min, Sw -------
__global__ __launch_bounds__(256) void k_prepw(const float* __restrict__ w) {
    int o = blockIdx.x;
    int tid = threadIdx.x;
    __shared__ float  sv[Dn];
    __shared__ float  ss[Dn];
    __shared__ float  pma[Dn];
    __shared__ float  pmb[Dn];
    __shared__ double sa[Dn];
    __shared__ double sb[Dn];
    for (int i = tid; i < Dn; i += 256) {
        float v = w[i * On + o];
        sv[i] = v;
        ss[i] = v;
    }
    __syncthreads();
    // bitonic sort ascending (n=512, 256 threads)
    for (int k = 2; k <= Dn; k <<= 1) {
        for (int j = k >> 1; j > 0; j >>= 1) {
            for (int t2 = tid; t2 < Dn; t2 += 256) {
                int ixj = t2 ^ j;
                if (ixj > t2) {
                    bool up = ((t2 & k) == 0);
                    float a = ss[t2], b2 = ss[ixj];
                    if ((a > b2) == up) { ss[t2] = b2; ss[ixj] = a; }
                }
            }
            __syncthreads();
        }
    }
    // parallel prefix-min (original order) + suffix-sum (sorted, double)
    for (int i = tid; i < Dn; i += 256) {
        pma[i] = sv[i];
        sa[i] = (double)ss[i];
    }
    __syncthreads();
    bool ping = true;
    for (int off = 1; off < Dn; off <<= 1) {
        float*  psrc = ping ? pma : pmb;
        float*  pdst = ping ? pmb : pma;
        double* ssrc = ping ? sa : sb;
        double* sdst = ping ? sb : sa;
        for (int i = tid; i < Dn; i += 256) {
            pdst[i] = (i >= off) ? fminf(psrc[i], psrc[i - off]) : psrc[i];
            sdst[i] = (i + off < Dn) ? ssrc[i] + ssrc[i + off] : ssrc[i];
        }
        __syncthreads();
        ping = !ping;
    }
    float*  pfin = ping ? pma : pmb;
    double* sfin = ping ? sa : sb;
    for (int i = tid; i < Dn; i += 256) {
        g_pmin[o * Dn + i] = pfin[i];
        g_suf[o * (Dn + 1) + i] = sfin[i];
        g_ws[o * Dn + i] = ss[i];
    }
    if (tid == 0) {
        g_suf[o * (Dn + 1) + Dn] = 0.0;
        g_Sw[o] = (double)Dn - sfin[0];   // sum_d (1 - w) = D - sum_d w
    }
}

// ---------------- rel_x numerator partials: sum_b max(x,t) ---------------
// grid (O/32=8, D/32=16, 4 b-splits); block 256 = 16x16; micro 2x2 (d x o)
__global__ __launch_bounds__(256) void k_relx(const float* __restrict__ x,
                                              const float* __restrict__ t) {
    int o0 = blockIdx.x * 32;
    int d0 = blockIdx.y * 32;
    int bs = blockIdx.z;
    __shared__ float xs[32][34];  // [b][d]
    __shared__ float ts[32][34];  // [b][o]
    int tid = threadIdx.x;
    int tx = tid & 15;   // o pair
    int ty = tid >> 4;   // d pair
    double a00 = 0, a01 = 0, a10 = 0, a11 = 0;
    int bbeg = bs * 256;
    for (int bc = bbeg; bc < bbeg + 256; bc += 32) {
        __syncthreads();
        for (int idx = tid; idx < 1024; idx += 256) {
            int i = idx >> 5, j = idx & 31;
            xs[i][j] = x[(bc + i) * Dn + d0 + j];
            ts[i][j] = t[(bc + i) * On + o0 + j];
        }
        __syncthreads();
        float f00 = 0, f01 = 0, f10 = 0, f11 = 0;
#pragma unroll
        for (int kb = 0; kb < 32; kb++) {
            float2 xv = *(const float2*)&xs[kb][2 * ty];
            float2 tv = *(const float2*)&ts[kb][2 * tx];
            f00 += fmaxf(xv.x, tv.x);
            f01 += fmaxf(xv.x, tv.y);
            f10 += fmaxf(xv.y, tv.x);
            f11 += fmaxf(xv.y, tv.y);
        }
        a00 += (double)f00; a01 += (double)f01;
        a10 += (double)f10; a11 += (double)f11;
    }
    int d_ = d0 + 2 * ty;
    int o_ = o0 + 2 * tx;
    double* p = g_rxp + (size_t)bs * DO;
    p[d_ * On + o_]           = a00;
    p[d_ * On + o_ + 1]       = a01;
    p[(d_ + 1) * On + o_]     = a10;
    p[(d_ + 1) * On + o_ + 1] = a11;
}

__global__ __launch_bounds__(256) void k_combRelx() {
    int i = blockIdx.x * 256 + threadIdx.x;   // DO/256 = 512 blocks
    int d = i >> 8;                           // On = 256
    double a = g_rxp[i] + g_rxp[DO + i] + g_rxp[2 * DO + i] + g_rxp[3 * DO + i];
    g_relx[i] = (float)(1.0 - ((double)Bn - a) / g_Sx[d]);
}

// ---------------- ind_x partials over 128-d splits ----------------
// grid (O/32=8, B/32=32, 4 d-splits); block 256; micro 2x2 (b x o)
__global__ __launch_bounds__(256) void k_indx(const float* __restrict__ x) {
    int o0 = blockIdx.x * 32;
    int b0 = blockIdx.y * 32;
    int ds = blockIdx.z;
    __shared__ float xs[32][34];  // [b][d-chunk]
    __shared__ float rs[32][34];  // [d-chunk][o]
    int tid = threadIdx.x;
    int tx = tid & 15;   // o pair
    int ty = tid >> 4;   // b pair
    float v00 = 3.0e38f, v01 = 3.0e38f, v10 = 3.0e38f, v11 = 3.0e38f;
    int i00 = 0, i01 = 0, i10 = 0, i11 = 0;
    int dbeg = ds * 128;
    for (int dc = dbeg; dc < dbeg + 128; dc += 32) {
        __syncthreads();
        for (int idx = tid; idx < 1024; idx += 256) {
            int i = idx >> 5, j = idx & 31;
            xs[i][j] = x[(b0 + i) * Dn + dc + j];
            rs[i][j] = g_relx[(dc + i) * On + o0 + j];
        }
        __syncthreads();
#pragma unroll
        for (int kd = 0; kd < 32; kd++) {
            float xv0 = xs[2 * ty][kd];
            float xv1 = xs[2 * ty + 1][kd];
            float2 rv = *(const float2*)&rs[kd][2 * tx];
            int dg = dc + kd;
            float v;
            v = fmaxf(xv0, rv.x); if (v < v00) { v00 = v; i00 = dg; }
            v = fmaxf(xv0, rv.y); if (v < v01) { v01 = v; i01 = dg; }
            v = fmaxf(xv1, rv.x); if (v < v10) { v10 = v; i10 = dg; }
            v = fmaxf(xv1, rv.y); if (v < v11) { v11 = v; i11 = dg; }
        }
    }
    int b_ = b0 + 2 * ty;
    int o_ = o0 + 2 * tx;
    float* vp = g_vp + (size_t)ds * BO;
    int*   ip = g_ip + (size_t)ds * BO;
    vp[b_ * On + o_] = v00;             ip[b_ * On + o_] = i00;
    vp[b_ * On + o_ + 1] = v01;         ip[b_ * On + o_ + 1] = i01;
    vp[(b_ + 1) * On + o_] = v10;       ip[(b_ + 1) * On + o_] = i10;
    vp[(b_ + 1) * On + o_ + 1] = v11;   ip[(b_ + 1) * On + o_ + 1] = i11;
}

__global__ __launch_bounds__(256) void k_combIndx(const float* __restrict__ x,
                                                  const float* __restrict__ w,
                                                  float* __restrict__ out) {
    int i = blockIdx.x * 256 + threadIdx.x;   // BO/256 = 1024 blocks
    int b = i >> 8;
    int o = i & 255;
    float bv = g_vp[i];
    int bi = g_ip[i];
#pragma unroll
    for (int s = 1; s < 4; s++) {
        float v = g_vp[s * BO + i];
        if (v < bv) { bv = v; bi = g_ip[s * BO + i]; }
    }
    out[i] = fmaxf(x[b * Dn + bi], w[bi * On + o]);
}

// ---------------- rel_w / ind_w / chosen_w via sorted + prefix-min -------
__global__ __launch_bounds__(256) void k_wout(const float* __restrict__ x,
                                              const float* __restrict__ w,
                                              const float* __restrict__ t,
                                              float* __restrict__ out) {
    int o = blockIdx.x;
    int tid = threadIdx.x;
    __shared__ float  ws[Dn];
    __shared__ float  pm[Dn];
    __shared__ double suf[Dn + 1];
    for (int i = tid; i < Dn; i += 256) {
        ws[i] = g_ws[o * Dn + i];
        pm[i] = g_pmin[o * Dn + i];
    }
    for (int i = tid; i < Dn + 1; i += 256)
        suf[i] = g_suf[o * (Dn + 1) + i];
    __syncthreads();
    double Sw = g_Sw[o];
    float gm = pm[Dn - 1];  // global min of column
    for (int b = tid; b < Bn; b += 256) {
        float tv = t[b * On + o];
        // c = count of sorted w <= tv
        int lo = 0, hi = Dn;
        while (lo < hi) {
            int m = (lo + hi) >> 1;
            if (ws[m] <= tv) lo = m + 1; else hi = m;
        }
        int c = lo;
        double N = (double)c * (double)tv + suf[c];
        float thr = (float)(1.0 - ((double)Dn - N) / Sw);  // rel_w
        int ind;
        if (gm <= thr) {
            lo = 0; hi = Dn - 1;
            while (lo < hi) {
                int m = (lo + hi) >> 1;
                if (pm[m] <= thr) hi = m; else lo = m + 1;
            }
            ind = lo;
        } else {
            lo = 0; hi = Dn - 1;
            while (lo < hi) {
                int m = (lo + hi) >> 1;
                if (pm[m] <= gm) hi = m; else lo = m + 1;
            }
            ind = lo;
        }
        out[BO + b * On + o] = fmaxf(x[b * Dn + ind], w[ind * On + o]);
    }
}

extern "C" void kernel_launch(void* const* d_in, const int* in_sizes, int n_in,
                              void* d_out, int out_size) {
    (void)in_sizes; (void)n_in; (void)out_size;
    const float* x = (const float*)d_in[0];
    const float* w = (const float*)d_in[1];
    const float* t = (const float*)d_in[2];
    float* out = (float*)d_out;

    k_prepx_part<<<dim3(16, 8), 256>>>(x);
    k_combSx<<<2, 256>>>();
    k_prepw<<<On, 256>>>(w);
    k_relx<<<dim3(On / 32, Dn / 32, 4), 256>>>(x, t);
    k_combRelx<<<DO / 256, 256>>>();
    k_indx<<<dim3(On / 32, Bn / 32, 4), 256>>>(x);
    k_combIndx<<<BO / 256, 256>>>(x, w, out);
    k_wout<<<On, 256>>>(x, w, t, out);
}

// round 4
// speedup vs baseline: 2.0304x; 1.2170x over previous
#include <cuda_runtime.h>
#include <cuda_bf16.h>

#define Bn 1024
#define Dn 512
#define On 256
#define BO (Bn * On)
#define DO (Dn * On)

// ---------------- device scratch (no allocations allowed) ----------------
__device__ float  g_SxP[8 * Dn];            // partial sums of (1-x) per 128-b chunk
__device__ double g_Sx[Dn];                 // sum_b (1 - x[b,d])
__device__ double g_rxp[8 * DO];            // rel_x numerator partials (per 128-b split)
__device__ float  g_relxT[On * Dn];         // rel_x transposed [o][d]

// ---------------- Sx partials: tiled transpose reduction -----------------
// grid (Dn/32=16, 8 b-splits), block 256 (32 d x 8 rows)
__global__ __launch_bounds__(256) void k_prepx_part(const float* __restrict__ x) {
    int d0 = blockIdx.x * 32;
    int bs = blockIdx.y;                  // 128 b's per split
    int dt = threadIdx.x & 31;
    int rt = threadIdx.x >> 5;            // 0..7
    int b0 = bs * 128 + rt * 16;
    float s = 0.0f;
#pragma unroll
    for (int k = 0; k < 16; k++)
        s += 1.0f - x[(b0 + k) * Dn + d0 + dt];
    __shared__ float sh[8][33];
    sh[rt][dt] = s;
    __syncthreads();
    if (rt == 0) {
        float acc = 0.0f;
#pragma unroll
        for (int r = 0; r < 8; r++) acc += sh[r][dt];
        g_SxP[bs * Dn + d0 + dt] = acc;
    }
}

__global__ __launch_bounds__(256) void k_combSx() {
    int d = blockIdx.x * 256 + threadIdx.x;
    if (d < Dn) {
        double s = 0.0;
#pragma unroll
        for (int i = 0; i < 8; i++) s += (double)g_SxP[i * Dn + d];
        g_Sx[d] = s;
    }
}

// ---------------- rel_x numerator partials: sum_b max(x,t) ---------------
// grid (On/64=4, Dn/64=8, 8 b-splits); block 256 = 16(tx:o) x 16(ty:d); micro 4x4
__global__ __launch_bounds__(256, 2) void k_relx(const float* __restrict__ x,
                                                 const float* __restrict__ t) {
    int o0 = blockIdx.x * 64;
    int d0 = blockIdx.y * 64;
    int bs = blockIdx.z;
    __shared__ float xs[32][68];  // [b][d 64]
    __shared__ float ts[32][68];  // [b][o 64]
    int tid = threadIdx.x;
    int tx = tid & 15;   // o quad
    int ty = tid >> 4;   // d quad
    double a[16];
#pragma unroll
    for (int k = 0; k < 16; k++) a[k] = 0.0;
    for (int chunk = 0; chunk < 4; chunk++) {
        int bc = bs * 128 + chunk * 32;
        __syncthreads();
        for (int u = tid; u < 512; u += 256) {
            int r = u >> 4, c = u & 15;
            *(float4*)&xs[r][c * 4] = *(const float4*)&x[(bc + r) * Dn + d0 + c * 4];
            *(float4*)&ts[r][c * 4] = *(const float4*)&t[(bc + r) * On + o0 + c * 4];
        }
        __syncthreads();
        float f[16];
#pragma unroll
        for (int k = 0; k < 16; k++) f[k] = 0.0f;
#pragma unroll
        for (int kb = 0; kb < 32; kb++) {
            float4 xv = *(const float4*)&xs[kb][ty * 4];
            float4 tv = *(const float4*)&ts[kb][tx * 4];
            f[0]  += fmaxf(xv.x, tv.x);  f[1]  += fmaxf(xv.x, tv.y);
            f[2]  += fmaxf(xv.x, tv.z);  f[3]  += fmaxf(xv.x, tv.w);
            f[4]  += fmaxf(xv.y, tv.x);  f[5]  += fmaxf(xv.y, tv.y);
            f[6]  += fmaxf(xv.y, tv.z);  f[7]  += fmaxf(xv.y, tv.w);
            f[8]  += fmaxf(xv.z, tv.x);  f[9]  += fmaxf(xv.z, tv.y);
            f[10] += fmaxf(xv.z, tv.z);  f[11] += fmaxf(xv.z, tv.w);
            f[12] += fmaxf(xv.w, tv.x);  f[13] += fmaxf(xv.w, tv.y);
            f[14] += fmaxf(xv.w, tv.z);  f[15] += fmaxf(xv.w, tv.w);
        }
#pragma unroll
        for (int k = 0; k < 16; k++) a[k] += (double)f[k];
    }
    double* p = g_rxp + (size_t)bs * DO;
#pragma unroll
    for (int i = 0; i < 4; i++) {
        int d_ = d0 + ty * 4 + i;
        int o_ = o0 + tx * 4;
#pragma unroll
        for (int j = 0; j < 4; j += 2) {
            double2 v2; v2.x = a[i * 4 + j]; v2.y = a[i * 4 + j + 1];
            *(double2*)&p[d_ * On + o_ + j] = v2;
        }
    }
}

// ---------------- combine rel_x partials + transpose to [o][d] -----------
// grid (Dn/32=16, On/32=8), block 256
__global__ __launch_bounds__(256) void k_transRel() {
    __shared__ float sm[32][33];
    int d0 = blockIdx.x * 32;
    int o0 = blockIdx.y * 32;
    int c = threadIdx.x & 31;
    int r8 = threadIdx.x >> 5;
    for (int rr = r8; rr < 32; rr += 8) {
        int d = d0 + rr, o = o0 + c;
        double a = 0.0;
#pragma unroll
        for (int s = 0; s < 8; s++) a += g_rxp[(size_t)s * DO + d * On + o];
        sm[rr][c] = (float)(1.0 - ((double)Bn - a) / g_Sx[d]);
    }
    __syncthreads();
    for (int rr = r8; rr < 32; rr += 8) {
        g_relxT[(o0 + rr) * Dn + (d0 + c)] = sm[c][rr];
    }
}

// ---------------- x-side: sort rel_x column, early-exit argmin walk ------
// one block per o; 256 threads
__global__ __launch_bounds__(256) void k_sortwalk(const float* __restrict__ x,
                                                  const float* __restrict__ w,
                                                  float* __restrict__ out) {
    int o = blockIdx.x;
    int tid = threadIdx.x;
    __shared__ float rk[Dn];
    __shared__ int   ri[Dn];
    for (int i = tid; i < Dn; i += 256) {
        rk[i] = g_relxT[o * Dn + i];
        ri[i] = i;
    }
    __syncthreads();
    // bitonic sort ascending by key, carry index
    for (int k = 2; k <= Dn; k <<= 1) {
        for (int j = k >> 1; j > 0; j >>= 1) {
            for (int t2 = tid; t2 < Dn; t2 += 256) {
                int ixj = t2 ^ j;
                if (ixj > t2) {
                    bool up = ((t2 & k) == 0);
                    float ka = rk[t2], kb2 = rk[ixj];
                    if ((ka > kb2) == up) {
                        rk[t2] = kb2; rk[ixj] = ka;
                        int ia = ri[t2]; ri[t2] = ri[ixj]; ri[ixj] = ia;
                    }
                }
            }
            __syncthreads();
        }
    }
    // walk: argmin_d max(x[b,d], rel_x[d,o]) with first-occurrence ties
    for (int b = tid; b < Bn; b += 256) {
        const float* xrow = x + b * Dn;
        float bv = 3.4e38f;
        int bd = Dn;
        for (int k = 0; k < Dn; k++) {
            float r = rk[k];
            if (r > bv) break;
            int d = ri[k];
            float v = fmaxf(xrow[d], r);
            if (v < bv || (v == bv && d < bd)) { bv = v; bd = d; }
        }
        out[b * On + o] = fmaxf(xrow[bd], w[bd * On + o]);
    }
}

// ---------------- w-side fused: sort w col, scans, binary-search walk ----
// one block per o; 256 threads
__global__ __launch_bounds__(256) void k_wfused(const float* __restrict__ x,
                                                const float* __restrict__ w,
                                                const float* __restrict__ t,
                                                float* __restrict__ out) {
    int o = blockIdx.x;
    int tid = threadIdx.x;
    __shared__ float  sv[Dn];     // original order
    __shared__ float  ss[Dn];     // sorted ascending
    __shared__ float  pma[Dn];
    __shared__ float  pmb[Dn];
    __shared__ double sa[Dn];
    __shared__ double sb[Dn];
    for (int i = tid; i < Dn; i += 256) {
        float v = w[i * On + o];
        sv[i] = v;
        ss[i] = v;
    }
    __syncthreads();
    // bitonic sort ascending
    for (int k = 2; k <= Dn; k <<= 1) {
        for (int j = k >> 1; j > 0; j >>= 1) {
            for (int t2 = tid; t2 < Dn; t2 += 256) {
                int ixj = t2 ^ j;
                if (ixj > t2) {
                    bool up = ((t2 & k) == 0);
                    float a = ss[t2], b2 = ss[ixj];
                    if ((a > b2) == up) { ss[t2] = b2; ss[ixj] = a; }
                }
            }
            __syncthreads();
        }
    }
    // parallel prefix-min (original order) + suffix-sum (sorted, double)
    for (int i = tid; i < Dn; i += 256) {
        pma[i] = sv[i];
        sa[i] = (double)ss[i];
    }
    __syncthreads();
    bool ping = true;
    for (int off = 1; off < Dn; off <<= 1) {
        float*  psrc = ping ? pma : pmb;
        float*  pdst = ping ? pmb : pma;
        double* ssrc = ping ? sa : sb;
        double* sdst = ping ? sb : sa;
        for (int i = tid; i < Dn; i += 256) {
            pdst[i] = (i >= off) ? fminf(psrc[i], psrc[i - off]) : psrc[i];
            sdst[i] = (i + off < Dn) ? ssrc[i] + ssrc[i + off] : ssrc[i];
        }
        __syncthreads();
        ping = !ping;
    }
    float*  pm  = ping ? pma : pmb;
    double* suf = ping ? sa : sb;
    double Sw = (double)Dn - suf[0];   // sum_d (1 - w) = D - sum_d w
    float gm = pm[Dn - 1];             // global min of column
    for (int b = tid; b < Bn; b += 256) {
        float tv = t[b * On + o];
        // c = count of sorted w <= tv
        int lo = 0, hi = Dn;
        while (lo < hi) {
            int m = (lo + hi) >> 1;
            if (ss[m] <= tv) lo = m + 1; else hi = m;
        }
        int c = lo;
        double sufc = (c < Dn) ? suf[c] : 0.0;
        double N = (double)c * (double)tv + sufc;
        float thr = (float)(1.0 - ((double)Dn - N) / Sw);  // rel_w
        int ind;
        if (gm <= thr) {
            lo = 0; hi = Dn - 1;
            while (lo < hi) {
                int m = (lo + hi) >> 1;
                if (pm[m] <= thr) hi = m; else lo = m + 1;
            }
            ind = lo;
        } else {
            lo = 0; hi = Dn - 1;
            while (lo < hi) {
                int m = (lo + hi) >> 1;
                if (pm[m] <= gm) hi = m; else lo = m + 1;
            }
            ind = lo;
        }
        out[BO + b * On + o] = fmaxf(x[b * Dn + ind], w[ind * On + o]);
    }
}

extern "C" void kernel_launch(void* const* d_in, const int* in_sizes, int n_in,
                              void* d_out, int out_size) {
    (void)in_sizes; (void)n_in; (void)out_size;
    const float* x = (const float*)d_in[0];
    const float* w = (const float*)d_in[1];
    const float* t = (const float*)d_in[2];
    float* out = (float*)d_out;

    k_prepx_part<<<dim3(16, 8), 256>>>(x);
    k_combSx<<<2, 256>>>();
    k_relx<<<dim3(On / 64, Dn / 64, 8), 256>>>(x, t);
    k_transRel<<<dim3(Dn / 32, On / 32), 256>>>();
    k_sortwalk<<<On, 256>>>(x, w, out);
    k_wfused<<<On, 256>>>(x, w, t, out);
}

// round 5
// speedup vs baseline: 2.6737x; 1.3168x over previous
#include <cuda_runtime.h>
#include <cuda_bf16.h>

#define Bn 1024
#define Dn 512
#define On 256
#define BO (Bn * On)
#define DO (Dn * On)

// ---------------- device scratch (no allocations allowed) ----------------
__device__ float  g_SxP[8 * Dn];            // partial sums of (1-x) per 128-b chunk
__device__ float  g_rxpF[8 * DO];           // rel_x numerator partials (per 128-b split)
__device__ float  g_relxT[On * Dn];         // rel_x transposed [o][d]

// ---------------- Sx partials: tiled transpose reduction -----------------
// grid (Dn/32=16, 8 b-splits), block 256 (32 d x 8 rows)
__global__ __launch_bounds__(256) void k_prepx_part(const float* __restrict__ x) {
    int d0 = blockIdx.x * 32;
    int bs = blockIdx.y;                  // 128 b's per split
    int dt = threadIdx.x & 31;
    int rt = threadIdx.x >> 5;            // 0..7
    int b0 = bs * 128 + rt * 16;
    float s = 0.0f;
#pragma unroll
    for (int k = 0; k < 16; k++)
        s += 1.0f - x[(b0 + k) * Dn + d0 + dt];
    __shared__ float sh[8][33];
    sh[rt][dt] = s;
    __syncthreads();
    if (rt == 0) {
        float acc = 0.0f;
#pragma unroll
        for (int r = 0; r < 8; r++) acc += sh[r][dt];
        g_SxP[bs * Dn + d0 + dt] = acc;
    }
}

// ---------------- rel_x numerator partials: sum_b max(x,t) ---------------
// grid (On/64=4, Dn/64=8, 8 b-splits); block 256 = 16(tx:o) x 16(ty:d); micro 4x4
__global__ __launch_bounds__(256, 2) void k_relx(const float* __restrict__ x,
                                                 const float* __restrict__ t) {
    int o0 = blockIdx.x * 64;
    int d0 = blockIdx.y * 64;
    int bs = blockIdx.z;
    __shared__ float xs[32][68];  // [b][d 64]
    __shared__ float ts[32][68];  // [b][o 64]
    int tid = threadIdx.x;
    int tx = tid & 15;   // o quad
    int ty = tid >> 4;   // d quad
    double a[16];
#pragma unroll
    for (int k = 0; k < 16; k++) a[k] = 0.0;
    for (int chunk = 0; chunk < 4; chunk++) {
        int bc = bs * 128 + chunk * 32;
        __syncthreads();
        for (int u = tid; u < 512; u += 256) {
            int r = u >> 4, c = u & 15;
            *(float4*)&xs[r][c * 4] = *(const float4*)&x[(bc + r) * Dn + d0 + c * 4];
            *(float4*)&ts[r][c * 4] = *(const float4*)&t[(bc + r) * On + o0 + c * 4];
        }
        __syncthreads();
        float f[16];
#pragma unroll
        for (int k = 0; k < 16; k++) f[k] = 0.0f;
#pragma unroll
        for (int kb = 0; kb < 32; kb++) {
            float4 xv = *(const float4*)&xs[kb][ty * 4];
            float4 tv = *(const float4*)&ts[kb][tx * 4];
            f[0]  += fmaxf(xv.x, tv.x);  f[1]  += fmaxf(xv.x, tv.y);
            f[2]  += fmaxf(xv.x, tv.z);  f[3]  += fmaxf(xv.x, tv.w);
            f[4]  += fmaxf(xv.y, tv.x);  f[5]  += fmaxf(xv.y, tv.y);
            f[6]  += fmaxf(xv.y, tv.z);  f[7]  += fmaxf(xv.y, tv.w);
            f[8]  += fmaxf(xv.z, tv.x);  f[9]  += fmaxf(xv.z, tv.y);
            f[10] += fmaxf(xv.z, tv.z);  f[11] += fmaxf(xv.z, tv.w);
            f[12] += fmaxf(xv.w, tv.x);  f[13] += fmaxf(xv.w, tv.y);
            f[14] += fmaxf(xv.w, tv.z);  f[15] += fmaxf(xv.w, tv.w);
        }
#pragma unroll
        for (int k = 0; k < 16; k++) a[k] += (double)f[k];
    }
    float* p = g_rxpF + (size_t)bs * DO;
#pragma unroll
    for (int i = 0; i < 4; i++) {
        int d_ = d0 + ty * 4 + i;
        int o_ = o0 + tx * 4;
        float4 v4;
        v4.x = (float)a[i * 4 + 0];
        v4.y = (float)a[i * 4 + 1];
        v4.z = (float)a[i * 4 + 2];
        v4.w = (float)a[i * 4 + 3];
        *(float4*)&p[d_ * On + o_] = v4;
    }
}

// ---------------- combine rel_x partials (+Sx) + transpose to [o][d] -----
// one thread per element; grid DO/256 = 512 blocks
__global__ __launch_bounds__(256) void k_transRel() {
    int i = blockIdx.x * 256 + threadIdx.x;  // [d][o] linear
    int d = i >> 8;
    int o = i & 255;
    double a = 0.0;
#pragma unroll
    for (int s = 0; s < 8; s++) a += (double)g_rxpF[(size_t)s * DO + i];
    double sx = 0.0;
#pragma unroll
    for (int s = 0; s < 8; s++) sx += (double)g_SxP[s * Dn + d];  // broadcast loads
    g_relxT[o * Dn + d] = (float)(1.0 - ((double)Bn - a) / sx);
}

// ---------------- solve both sides: grid 512 -----------------------------
// blocks [0,256): x-side  (sort rel_x col, early-exit argmin walk)
// blocks [256,512): w-side (sort w col, scans, binary-search walk)
__global__ __launch_bounds__(256) void k_solve(const float* __restrict__ x,
                                               const float* __restrict__ w,
                                               const float* __restrict__ t,
                                               float* __restrict__ out) {
    int o = blockIdx.x & 255;
    int tid = threadIdx.x;
    __shared__ float  rk[Dn];
    __shared__ int    ri[Dn];
    __shared__ float  sv[Dn];
    __shared__ float  pma[Dn];
    __shared__ float  pmb[Dn];
    __shared__ double sa[Dn];
    __shared__ double sb[Dn];

    if (blockIdx.x < 256) {
        // ------------------ x-side ------------------
        for (int i = tid; i < Dn; i += 256) {
            rk[i] = g_relxT[o * Dn + i];
            ri[i] = i;
        }
        __syncthreads();
        // bitonic sort ascending by key, carry index
        for (int k = 2; k <= Dn; k <<= 1) {
            for (int j = k >> 1; j > 0; j >>= 1) {
                for (int t2 = tid; t2 < Dn; t2 += 256) {
                    int ixj = t2 ^ j;
                    if (ixj > t2) {
                        bool up = ((t2 & k) == 0);
                        float ka = rk[t2], kb2 = rk[ixj];
                        if ((ka > kb2) == up) {
                            rk[t2] = kb2; rk[ixj] = ka;
                            int ia = ri[t2]; ri[t2] = ri[ixj]; ri[ixj] = ia;
                        }
                    }
                }
                __syncthreads();
            }
        }
        // walk: argmin_d max(x[b,d], rel_x[d,o]), first-occurrence ties
        for (int b = tid; b < Bn; b += 256) {
            const float* xrow = x + b * Dn;
            float bv = 3.4e38f;
            int bd = Dn;
            for (int k = 0; k < Dn; k++) {
                float r = rk[k];
                if (r > bv) break;
                int d = ri[k];
                float v = fmaxf(xrow[d], r);
                if (v < bv || (v == bv && d < bd)) { bv = v; bd = d; }
            }
            out[b * On + o] = fmaxf(xrow[bd], w[bd * On + o]);
        }
    } else {
        // ------------------ w-side ------------------
        float* ss = rk;  // reuse as sorted array
        for (int i = tid; i < Dn; i += 256) {
            float v = w[i * On + o];
            sv[i] = v;
            ss[i] = v;
        }
        __syncthreads();
        // bitonic sort ascending
        for (int k = 2; k <= Dn; k <<= 1) {
            for (int j = k >> 1; j > 0; j >>= 1) {
                for (int t2 = tid; t2 < Dn; t2 += 256) {
                    int ixj = t2 ^ j;
                    if (ixj > t2) {
                        bool up = ((t2 & k) == 0);
                        float a = ss[t2], b2 = ss[ixj];
                        if ((a > b2) == up) { ss[t2] = b2; ss[ixj] = a; }
                    }
                }
                __syncthreads();
            }
        }
        // parallel prefix-min (original order) + suffix-sum (sorted, double)
        for (int i = tid; i < Dn; i += 256) {
            pma[i] = sv[i];
            sa[i] = (double)ss[i];
        }
        __syncthreads();
        bool ping = true;
        for (int off = 1; off < Dn; off <<= 1) {
            float*  psrc = ping ? pma : pmb;
            float*  pdst = ping ? pmb : pma;
            double* ssrc = ping ? sa : sb;
            double* sdst = ping ? sb : sa;
            for (int i = tid; i < Dn; i += 256) {
                pdst[i] = (i >= off) ? fminf(psrc[i], psrc[i - off]) : psrc[i];
                sdst[i] = (i + off < Dn) ? ssrc[i] + ssrc[i + off] : ssrc[i];
            }
            __syncthreads();
            ping = !ping;
        }
        float*  pm  = ping ? pma : pmb;
        double* suf = ping ? sa : sb;
        double Sw = (double)Dn - suf[0];   // sum_d (1 - w) = D - sum_d w
        float gm = pm[Dn - 1];             // global min of column
        for (int b = tid; b < Bn; b += 256) {
            float tv = t[b * On + o];
            // c = count of sorted w <= tv
            int lo = 0, hi = Dn;
            while (lo < hi) {
                int m = (lo + hi) >> 1;
                if (ss[m] <= tv) lo = m + 1; else hi = m;
            }
            int c = lo;
            double sufc = (c < Dn) ? suf[c] : 0.0;
            double N = (double)c * (double)tv + sufc;
            float thr = (float)(1.0 - ((double)Dn - N) / Sw);  // rel_w
            int ind;
            if (gm <= thr) {
                lo = 0; hi = Dn - 1;
                while (lo < hi) {
                    int m = (lo + hi) >> 1;
                    if (pm[m] <= thr) hi = m; else lo = m + 1;
                }
                ind = lo;
            } else {
                lo = 0; hi = Dn - 1;
                while (lo < hi) {
                    int m = (lo + hi) >> 1;
                    if (pm[m] <= gm) hi = m; else lo = m + 1;
                }
                ind = lo;
            }
            out[BO + b * On + o] = fmaxf(x[b * Dn + ind], w[ind * On + o]);
        }
    }
}

extern "C" void kernel_launch(void* const* d_in, const int* in_sizes, int n_in,
                              void* d_out, int out_size) {
    (void)in_sizes; (void)n_in; (void)out_size;
    const float* x = (const float*)d_in[0];
    const float* w = (const float*)d_in[1];
    const float* t = (const float*)d_in[2];
    float* out = (float*)d_out;

    k_prepx_part<<<dim3(16, 8), 256>>>(x);
    k_relx<<<dim3(On / 64, Dn / 64, 8), 256>>>(x, t);
    k_transRel<<<DO / 256, 256>>>();
    k_solve<<<512, 256>>>(x, w, t, out);
}

// round 6
// speedup vs baseline: 2.9988x; 1.1216x over previous
#include <cuda_runtime.h>
#include <cuda_bf16.h>

#define Bn 1024
#define Dn 512
#define On 256
#define BO (Bn * On)
#define DO (Dn * On)

// ---------------- device scratch (no allocations allowed) ----------------
__device__ float  g_SxP[8 * Dn];            // partial sums of (1-x) per 128-b chunk
__device__ float  g_rxpF[8 * DO];           // rel_x numerator partials (per 128-b split)
__device__ float  g_relxT[On * Dn];         // rel_x transposed [o][d]
__device__ float  g_xT[Dn * Bn];            // x transposed [d][b]

// ---------------- Sx partials + x transpose ------------------------------
// grid (Dn/32=16, 8 b-splits), block 256
__global__ __launch_bounds__(256) void k_prepx_part(const float* __restrict__ x) {
    int d0 = blockIdx.x * 32;
    int bs = blockIdx.y;                  // 128 b's per split
    int b0 = bs * 128;
    int tid = threadIdx.x;
    __shared__ float tile[128][33];
    // load 128x32 tile coalesced
#pragma unroll
    for (int p = 0; p < 16; p++) {
        int idx = p * 256 + tid;
        int row = idx >> 5, col = idx & 31;
        tile[row][col] = x[(b0 + row) * Dn + d0 + col];
    }
    __syncthreads();
    // Sx partial (same chunk order as before: 16-b float chunks per rt)
    {
        int dt = tid & 31;
        int rt = tid >> 5;                // 0..7
        float s = 0.0f;
#pragma unroll
        for (int k = 0; k < 16; k++)
            s += 1.0f - tile[rt * 16 + k][dt];
        __shared__ float sh[8][33];
        sh[rt][dt] = s;
        __syncthreads();
        if (rt == 0) {
            float acc = 0.0f;
#pragma unroll
            for (int r = 0; r < 8; r++) acc += sh[r][dt];
            g_SxP[bs * Dn + d0 + dt] = acc;
        }
    }
    // xT write: coalesced along b
#pragma unroll
    for (int p = 0; p < 16; p++) {
        int idx = p * 256 + tid;
        int b = idx & 127, d = idx >> 7;   // 32 d rows
        g_xT[(d0 + d) * Bn + b0 + b] = tile[b][d];
    }
}

// ---------------- rel_x numerator partials: sum_b max(x,t) ---------------
// grid (On/64=4, Dn/64=8, 8 b-splits); block 256 = 16(tx:o) x 16(ty:d); micro 4x4
__global__ __launch_bounds__(256, 2) void k_relx(const float* __restrict__ x,
                                                 const float* __restrict__ t) {
    int o0 = blockIdx.x * 64;
    int d0 = blockIdx.y * 64;
    int bs = blockIdx.z;
    __shared__ float xs[32][68];  // [b][d 64]
    __shared__ float ts[32][68];  // [b][o 64]
    int tid = threadIdx.x;
    int tx = tid & 15;   // o quad
    int ty = tid >> 4;   // d quad
    double a[16];
#pragma unroll
    for (int k = 0; k < 16; k++) a[k] = 0.0;
    for (int chunk = 0; chunk < 4; chunk++) {
        int bc = bs * 128 + chunk * 32;
        __syncthreads();
        for (int u = tid; u < 512; u += 256) {
            int r = u >> 4, c = u & 15;
            *(float4*)&xs[r][c * 4] = *(const float4*)&x[(bc + r) * Dn + d0 + c * 4];
            *(float4*)&ts[r][c * 4] = *(const float4*)&t[(bc + r) * On + o0 + c * 4];
        }
        __syncthreads();
        float f[16];
#pragma unroll
        for (int k = 0; k < 16; k++) f[k] = 0.0f;
#pragma unroll
        for (int kb = 0; kb < 32; kb++) {
            float4 xv = *(const float4*)&xs[kb][ty * 4];
            float4 tv = *(const float4*)&ts[kb][tx * 4];
            f[0]  += fmaxf(xv.x, tv.x);  f[1]  += fmaxf(xv.x, tv.y);
            f[2]  += fmaxf(xv.x, tv.z);  f[3]  += fmaxf(xv.x, tv.w);
            f[4]  += fmaxf(xv.y, tv.x);  f[5]  += fmaxf(xv.y, tv.y);
            f[6]  += fmaxf(xv.y, tv.z);  f[7]  += fmaxf(xv.y, tv.w);
            f[8]  += fmaxf(xv.z, tv.x);  f[9]  += fmaxf(xv.z, tv.y);
            f[10] += fmaxf(xv.z, tv.z);  f[11] += fmaxf(xv.z, tv.w);
            f[12] += fmaxf(xv.w, tv.x);  f[13] += fmaxf(xv.w, tv.y);
            f[14] += fmaxf(xv.w, tv.z);  f[15] += fmaxf(xv.w, tv.w);
        }
#pragma unroll
        for (int k = 0; k < 16; k++) a[k] += (double)f[k];
    }
    float* p = g_rxpF + (size_t)bs * DO;
#pragma unroll
    for (int i = 0; i < 4; i++) {
        int d_ = d0 + ty * 4 + i;
        int o_ = o0 + tx * 4;
        float4 v4;
        v4.x = (float)a[i * 4 + 0];
        v4.y = (float)a[i * 4 + 1];
        v4.z = (float)a[i * 4 + 2];
        v4.w = (float)a[i * 4 + 3];
        *(float4*)&p[d_ * On + o_] = v4;
    }
}

// ---------------- combine rel_x partials (+Sx) + transpose to [o][d] -----
__global__ __launch_bounds__(256) void k_transRel() {
    int i = blockIdx.x * 256 + threadIdx.x;  // [d][o] linear
    int d = i >> 8;
    int o = i & 255;
    double a = 0.0;
#pragma unroll
    for (int s = 0; s < 8; s++) a += (double)g_rxpF[(size_t)s * DO + i];
    double sx = 0.0;
#pragma unroll
    for (int s = 0; s < 8; s++) sx += (double)g_SxP[s * Dn + d];  // broadcast loads
    g_relxT[o * Dn + d] = (float)(1.0 - ((double)Bn - a) / sx);
}

// ---------------- solve both sides: grid 512 -----------------------------
// blocks [0,256): x-side  (sort rel_x col, lockstep early-exit argmin walk)
// blocks [256,512): w-side (sort w col, scans, binary-search walk)
__global__ __launch_bounds__(256) void k_solve(const float* __restrict__ x,
                                               const float* __restrict__ w,
                                               const float* __restrict__ t,
                                               float* __restrict__ out) {
    int o = blockIdx.x & 255;
    int tid = threadIdx.x;
    __shared__ unsigned long long keys[Dn];   // x-side sort keys
    __shared__ float  sv[Dn];
    __shared__ float  pma[Dn];
    __shared__ float  pmb[Dn];
    __shared__ double sa[Dn];
    __shared__ double sb[Dn];

    if (blockIdx.x < 256) {
        // ------------------ x-side ------------------
        for (int i = tid; i < Dn; i += 256) {
            unsigned int kb = __float_as_uint(g_relxT[o * Dn + i]);  // rel in [0,1]
            keys[i] = ((unsigned long long)kb << 32) | (unsigned int)i;
        }
        __syncthreads();
        // bitonic sort ascending on packed keys
        for (int k = 2; k <= Dn; k <<= 1) {
            for (int j = k >> 1; j > 0; j >>= 1) {
                for (int t2 = tid; t2 < Dn; t2 += 256) {
                    int ixj = t2 ^ j;
                    if (ixj > t2) {
                        bool up = ((t2 & k) == 0);
                        unsigned long long ka = keys[t2], kb2 = keys[ixj];
                        if ((ka > kb2) == up) { keys[t2] = kb2; keys[ixj] = ka; }
                    }
                }
                __syncthreads();
            }
        }
        // lockstep chunked walk: argmin_d max(x[b,d], rel_x[d,o])
        for (int bb = 0; bb < 4; bb++) {
            int b = bb * 256 + tid;
            float bv = 3.4e38f;
            int bd = Dn;
            bool active = true;
            for (int k0 = 0; k0 < Dn; k0 += 8) {
                if (!__ballot_sync(0xFFFFFFFFu, active)) break;
                float rr[8], xv[8];
                int dd[8];
#pragma unroll
                for (int j = 0; j < 8; j++) {
                    unsigned long long key = keys[k0 + j];
                    rr[j] = __uint_as_float((unsigned int)(key >> 32));
                    dd[j] = (int)(key & 0xFFFFFFFFu);
                    xv[j] = g_xT[dd[j] * Bn + b];   // d uniform, b lane-consecutive
                }
#pragma unroll
                for (int j = 0; j < 8; j++) {
                    if (active) {
                        if (rr[j] > bv) { active = false; }
                        else {
                            float v = fmaxf(xv[j], rr[j]);
                            if (v < bv || (v == bv && dd[j] < bd)) { bv = v; bd = dd[j]; }
                        }
                    }
                }
            }
            out[b * On + o] = fmaxf(g_xT[bd * Bn + b], w[bd * On + o]);
        }
    } else {
        // ------------------ w-side ------------------
        float* ss = (float*)keys;  // reuse (2KB of the 4KB)
        for (int i = tid; i < Dn; i += 256) {
            float v = w[i * On + o];
            sv[i] = v;
            ss[i] = v;
        }
        __syncthreads();
        // bitonic sort ascending
        for (int k = 2; k <= Dn; k <<= 1) {
            for (int j = k >> 1; j > 0; j >>= 1) {
                for (int t2 = tid; t2 < Dn; t2 += 256) {
                    int ixj = t2 ^ j;
                    if (ixj > t2) {
                        bool up = ((t2 & k) == 0);
                        float a = ss[t2], b2 = ss[ixj];
                        if ((a > b2) == up) { ss[t2] = b2; ss[ixj] = a; }
                    }
                }
                __syncthreads();
            }
        }
        // parallel prefix-min (original order) + suffix-sum (sorted, double)
        for (int i = tid; i < Dn; i += 256) {
            pma[i] = sv[i];
            sa[i] = (double)ss[i];
        }
        __syncthreads();
        bool ping = true;
        for (int off = 1; off < Dn; off <<= 1) {
            float*  psrc = ping ? pma : pmb;
            float*  pdst = ping ? pmb : pma;
            double* ssrc = ping ? sa : sb;
            double* sdst = ping ? sb : sa;
            for (int i = tid; i < Dn; i += 256) {
                pdst[i] = (i >= off) ? fminf(psrc[i], psrc[i - off]) : psrc[i];
                sdst[i] = (i + off < Dn) ? ssrc[i] + ssrc[i + off] : ssrc[i];
            }
            __syncthreads();
            ping = !ping;
        }
        float*  pm  = ping ? pma : pmb;
        double* suf = ping ? sa : sb;
        double Sw = (double)Dn - suf[0];   // sum_d (1 - w) = D - sum_d w
        float gm = pm[Dn - 1];             // global min of column
        for (int b = tid; b < Bn; b += 256) {
            float tv = t[b * On + o];
            // c = count of sorted w <= tv
            int lo = 0, hi = Dn;
            while (lo < hi) {
                int m = (lo + hi) >> 1;
                if (ss[m] <= tv) lo = m + 1; else hi = m;
            }
            int c = lo;
            double sufc = (c < Dn) ? suf[c] : 0.0;
            double N = (double)c * (double)tv + sufc;
            float thr = (float)(1.0 - ((double)Dn - N) / Sw);  // rel_w
            int ind;
            if (gm <= thr) {
                lo = 0; hi = Dn - 1;
                while (lo < hi) {
                    int m = (lo + hi) >> 1;
                    if (pm[m] <= thr) hi = m; else lo = m + 1;
                }
                ind = lo;
            } else {
                lo = 0; hi = Dn - 1;
                while (lo < hi) {
                    int m = (lo + hi) >> 1;
                    if (pm[m] <= gm) hi = m; else lo = m + 1;
                }
                ind = lo;
            }
            out[BO + b * On + o] = fmaxf(x[b * Dn + ind], w[ind * On + o]);
        }
    }
}

extern "C" void kernel_launch(void* const* d_in, const int* in_sizes, int n_in,
                              void* d_out, int out_size) {
    (void)in_sizes; (void)n_in; (void)out_size;
    const float* x = (const float*)d_in[0];
    const float* w = (const float*)d_in[1];
    const float* t = (const float*)d_in[2];
    float* out = (float*)d_out;

    k_prepx_part<<<dim3(16, 8), 256>>>(x);
    k_relx<<<dim3(On / 64, Dn / 64, 8), 256>>>(x, t);
    k_transRel<<<DO / 256, 256>>>();
    k_solve<<<512, 256>>>(x, w, t, out);
}